// round 4
// baseline (speedup 1.0000x reference)
#include <cuda_runtime.h>
#include <math.h>

// ---------------- problem constants ----------------
#define BATCH 8
#define LX    512
#define SEQ   896           // total tokens per batch (512 x-tokens + 384 w-tokens)
#define DMODEL 1024
#define NHEAD 16
#define HDIM  64
#define FFDIM 4096
#define NLAY  4
#define HAM   144
#define MTOT  (BATCH*SEQ)   // 7168 rows

// ---------------- scratch (device globals: allocation-free) ----------------
static __device__ float g_tgt[(size_t)MTOT * DMODEL];          // 29.4 MB
static __device__ float g_qkv[(size_t)MTOT * 3 * DMODEL];      // 88 MB
static __device__ float g_scores[(size_t)BATCH * NHEAD * SEQ * SEQ]; // 411 MB
static __device__ float g_ctx[(size_t)MTOT * DMODEL];
static __device__ float g_tmp[(size_t)MTOT * DMODEL];
static __device__ float g_ff[(size_t)MTOT * FFDIM];            // 117 MB

// ---------------- helpers ----------------
__device__ __forceinline__ float neg_inf_f() { return __int_as_float(0xff800000); }

__device__ __forceinline__ unsigned long long pack2(float lo, float hi) {
    unsigned long long r;
    asm("mov.b64 %0, {%1, %2};" : "=l"(r) : "f"(lo), "f"(hi));
    return r;
}
__device__ __forceinline__ void unpack2(unsigned long long v, float& lo, float& hi) {
    asm("mov.b64 {%0, %1}, %2;" : "=f"(lo), "=f"(hi) : "l"(v));
}
// packed fp32x2 FMA: d = a*b + d  (2 FMAs per issue -> 2x fp32 throughput on sm_103a)
__device__ __forceinline__ void ffma2(unsigned long long& d, unsigned long long a, unsigned long long b) {
    asm("fma.rn.f32x2 %0, %1, %2, %0;" : "+l"(d) : "l"(a), "l"(b));
}
__device__ __forceinline__ float gelu_exact(float v) {
    return 0.5f * v * (1.0f + erff(v * 0.70710678118654752f));
}
// block reductions for 256-thread blocks (8 warps). sred must hold >=8 floats.
__device__ __forceinline__ float block_sum256(float val, float* sred) {
#pragma unroll
    for (int o = 16; o > 0; o >>= 1) val += __shfl_xor_sync(0xffffffffu, val, o);
    if ((threadIdx.x & 31) == 0) sred[threadIdx.x >> 5] = val;
    __syncthreads();
    float t = sred[0];
#pragma unroll
    for (int i = 1; i < 8; i++) t += sred[i];
    __syncthreads();
    return t;
}
__device__ __forceinline__ float block_max256(float val, float* sred) {
#pragma unroll
    for (int o = 16; o > 0; o >>= 1) val = fmaxf(val, __shfl_xor_sync(0xffffffffu, val, o));
    if ((threadIdx.x & 31) == 0) sred[threadIdx.x >> 5] = val;
    __syncthreads();
    float t = sred[0];
#pragma unroll
    for (int i = 1; i < 8; i++) t = fmaxf(t, sred[i]);
    __syncthreads();
    return t;
}

// ---------------- embed: tgt = [xx | ww] + PE ----------------
// one block per (b, s) row; 256 threads over the D=1024 outputs
__global__ void embed_kernel(const float* __restrict__ x, const float* __restrict__ w,
                             const float* __restrict__ Wn, const float* __restrict__ bn,
                             const float* __restrict__ Wc, const float* __restrict__ bc)
{
    const int row = blockIdx.x;                 // 0..7167
    const int b = row / SEQ, s = row % SEQ;
    const int tid = threadIdx.x;
    const float rinv = rsqrtf(1.0001f);         // 1/sqrt(1 + EPS_RMS)
    const float pefac = -6.90775527898213705f / 1024.0f;   // -ln(1000)/D
    __shared__ float feat[64];
    __shared__ float tpos_sh;

    if (s < LX) {
        if (tid < 64) {
            float v = x[((size_t)b * LX + s) * 64 + tid];
            if (v != v) v = 0.0f;                // nan_to_num
            if (tid == 0) tpos_sh = v;           // t = x[...,0]
            if (tid >= 1) {
                float u = v * rinv;
                feat[tid - 1] = fminf(fmaxf(u, -5.0f), 5.0f);
            }
        }
        __syncthreads();
        const float t = tpos_sh;
        for (int d = tid; d < DMODEL; d += 256) {
            const float* wr = Wn + (size_t)d * 63;
            float acc = bn[d];
#pragma unroll
            for (int j = 0; j < 63; j++) acc = fmaf(feat[j], wr[j], acc);
            float divf = expf((float)(d >> 1) * pefac);
            float ang = t * divf;
            acc += (d & 1) ? cosf(ang) : sinf(ang);
            g_tgt[(size_t)row * DMODEL + d] = acc;
        }
    } else {
        const int j = s - LX;                    // 0..383 -> w[b].reshape(384,6)
        if (tid < 6) {
            float v = w[(size_t)b * 2304 + (size_t)j * 6 + tid];
            if (v != v) v = 0.0f;
            float u = v * rinv;
            feat[tid] = fminf(fmaxf(u, -5.0f), 5.0f);
        }
        __syncthreads();
        const float pos = (float)s;              // global PE at position s
        for (int d = tid; d < DMODEL; d += 256) {
            const float* wr = Wc + (size_t)d * 6;
            float acc = bc[d];
#pragma unroll
            for (int jj = 0; jj < 6; jj++) acc = fmaf(feat[jj], wr[jj], acc);
            float divf = expf((float)(d >> 1) * pefac);
            float ang = pos * divf;
            acc += (d & 1) ? cosf(ang) : sinf(ang);
            g_tgt[(size_t)row * DMODEL + d] = acc;
        }
    }
}

// ---------------- main SGEMM (TN): C[M,N] = A[M,K] * B[N,K]^T + bias, opt GELU ----------------
// 128x128x8 tile, 256 threads, 8x8 per thread via f32x2 FMA pairs.
// Requires M%128==0, N%128==0, K%8==0 (all shapes here satisfy this).
__global__ void __launch_bounds__(256, 2) sgemm_tn_kernel(
    const float* __restrict__ A, int lda,
    const float* __restrict__ Bw, int ldb,
    float* __restrict__ C, int ldc,
    int K, const float* __restrict__ bias, int act)
{
    __shared__ __align__(16) float As[8][128];
    __shared__ __align__(16) float Bs[8][128];
    const int tid = threadIdx.x;
    const int tx = tid & 15, ty = tid >> 4;
    const int m0 = blockIdx.y * 128, n0 = blockIdx.x * 128;
    const int lr = tid >> 1, lk = (tid & 1) * 4;
    const float* Ap = A + (size_t)(m0 + lr) * lda + lk;
    const float* Bp = Bw + (size_t)(n0 + lr) * ldb + lk;

    unsigned long long acc[4][8];
#pragma unroll
    for (int i = 0; i < 4; i++)
#pragma unroll
        for (int j = 0; j < 8; j++) acc[i][j] = 0ull;

    for (int k0 = 0; k0 < K; k0 += 8) {
        float4 av = *(const float4*)(Ap + k0);
        float4 bv = *(const float4*)(Bp + k0);
        As[lk + 0][lr] = av.x; As[lk + 1][lr] = av.y; As[lk + 2][lr] = av.z; As[lk + 3][lr] = av.w;
        Bs[lk + 0][lr] = bv.x; Bs[lk + 1][lr] = bv.y; Bs[lk + 2][lr] = bv.z; Bs[lk + 3][lr] = bv.w;
        __syncthreads();
#pragma unroll
        for (int kk = 0; kk < 8; kk++) {
            unsigned long long a2[4];
#pragma unroll
            for (int i = 0; i < 4; i++)
                a2[i] = *(const unsigned long long*)&As[kk][ty * 8 + 2 * i];
            float4 b0 = *(const float4*)&Bs[kk][tx * 8];
            float4 b1 = *(const float4*)&Bs[kk][tx * 8 + 4];
            float bf[8] = {b0.x, b0.y, b0.z, b0.w, b1.x, b1.y, b1.z, b1.w};
#pragma unroll
            for (int j = 0; j < 8; j++) {
                unsigned long long b2 = pack2(bf[j], bf[j]);
#pragma unroll
                for (int i = 0; i < 4; i++) ffma2(acc[i][j], a2[i], b2);
            }
        }
        __syncthreads();
    }

    const int mbase = m0 + ty * 8;
    const int nbase = n0 + tx * 8;
#pragma unroll
    for (int j = 0; j < 8; j++) {
        const float bj = bias[nbase + j];
#pragma unroll
        for (int i = 0; i < 4; i++) {
            float lo, hi; unpack2(acc[i][j], lo, hi);
            lo += bj; hi += bj;
            if (act == 1) { lo = gelu_exact(lo); hi = gelu_exact(hi); }
            C[(size_t)(mbase + 2 * i) * ldc + nbase + j] = lo;
            C[(size_t)(mbase + 2 * i + 1) * ldc + nbase + j] = hi;
        }
    }
}

// ---------------- attention scores: per (b,h): S = Q K^T / 8, masked ----------------
// grid (7, 7, 128); same tile core, K=64, fused scale+mask epilogue
__global__ void __launch_bounds__(256, 2) attn_scores_kernel(const float* __restrict__ x)
{
    __shared__ __align__(16) float As[8][128];
    __shared__ __align__(16) float Bs[8][128];
    __shared__ bool colnan_s[128];
    const int z = blockIdx.z;
    const int b = z >> 4, h = z & 15;
    const float* A  = g_qkv + (size_t)b * SEQ * 3072 + h * 64;          // Q rows, stride 3072
    const float* Bw = A + 1024;                                          // K rows
    float* C = g_scores + (size_t)z * SEQ * SEQ;
    const int tid = threadIdx.x;
    const int tx = tid & 15, ty = tid >> 4;
    const int m0 = blockIdx.y * 128, n0 = blockIdx.x * 128;
    const int lr = tid >> 1, lk = (tid & 1) * 4;

    if (tid < 128) {
        int n = n0 + tid;
        bool cn = false;
        if (n < LX) { float vv = x[((size_t)b * LX + n) * 64]; cn = (vv != vv); }
        colnan_s[tid] = cn;
    }

    const float* Ap = A + (size_t)(m0 + lr) * 3072 + lk;
    const float* Bp = Bw + (size_t)(n0 + lr) * 3072 + lk;
    unsigned long long acc[4][8];
#pragma unroll
    for (int i = 0; i < 4; i++)
#pragma unroll
        for (int j = 0; j < 8; j++) acc[i][j] = 0ull;

    for (int k0 = 0; k0 < 64; k0 += 8) {
        float4 av = *(const float4*)(Ap + k0);
        float4 bv = *(const float4*)(Bp + k0);
        As[lk + 0][lr] = av.x; As[lk + 1][lr] = av.y; As[lk + 2][lr] = av.z; As[lk + 3][lr] = av.w;
        Bs[lk + 0][lr] = bv.x; Bs[lk + 1][lr] = bv.y; Bs[lk + 2][lr] = bv.z; Bs[lk + 3][lr] = bv.w;
        __syncthreads();
#pragma unroll
        for (int kk = 0; kk < 8; kk++) {
            unsigned long long a2[4];
#pragma unroll
            for (int i = 0; i < 4; i++)
                a2[i] = *(const unsigned long long*)&As[kk][ty * 8 + 2 * i];
            float4 b0 = *(const float4*)&Bs[kk][tx * 8];
            float4 b1 = *(const float4*)&Bs[kk][tx * 8 + 4];
            float bf[8] = {b0.x, b0.y, b0.z, b0.w, b1.x, b1.y, b1.z, b1.w};
#pragma unroll
            for (int j = 0; j < 8; j++) {
                unsigned long long b2 = pack2(bf[j], bf[j]);
#pragma unroll
                for (int i = 0; i < 4; i++) ffma2(acc[i][j], a2[i], b2);
            }
        }
        __syncthreads();
    }

    const int mbase = m0 + ty * 8;
    const int nbase = n0 + tx * 8;
    const float NI = neg_inf_f();
#pragma unroll
    for (int j = 0; j < 8; j++) {
        const int n = nbase + j;
        const bool cn = colnan_s[tx * 8 + j];
#pragma unroll
        for (int i = 0; i < 4; i++) {
            float lo, hi; unpack2(acc[i][j], lo, hi);
            const int mlo = mbase + 2 * i, mhi = mlo + 1;
            bool mask_lo = (n < LX) ? cn : (n > mlo);
            bool mask_hi = (n < LX) ? cn : (n > mhi);
            C[(size_t)mlo * SEQ + n] = mask_lo ? NI : lo * 0.125f;
            C[(size_t)mhi * SEQ + n] = mask_hi ? NI : hi * 0.125f;
        }
    }
}

// ---------------- softmax over rows of g_scores (len 896) ----------------
__global__ void softmax_kernel()
{
    const size_t row = blockIdx.x;               // B*H*S rows
    float* p = g_scores + row * SEQ;
    const int tid = threadIdx.x;
    __shared__ float sred[8];
    float v[4];
    float mx = neg_inf_f();
#pragma unroll
    for (int i = 0; i < 4; i++) {
        int c = tid + i * 256;
        v[i] = (c < SEQ) ? p[c] : neg_inf_f();
        mx = fmaxf(mx, v[i]);
    }
    mx = block_max256(mx, sred);
    float s = 0.0f;
#pragma unroll
    for (int i = 0; i < 4; i++) { v[i] = expf(v[i] - mx); s += v[i]; }
    s = block_sum256(s, sred);
    const float inv = 1.0f / s;
#pragma unroll
    for (int i = 0; i < 4; i++) {
        int c = tid + i * 256;
        if (c < SEQ) p[c] = v[i] * inv;
    }
}

// ---------------- attn @ V (NN gemm): per (b,h): O[896,64] -> g_ctx interleaved ----------------
// grid (14, 128); 64x64x16 tile, 256 threads, 4x4 per thread via f32x2
__global__ void __launch_bounds__(256) attn_av_kernel()
{
    __shared__ __align__(16) float As[16][64];
    __shared__ __align__(16) float Bs[16][64];
    const int z = blockIdx.y;
    const int b = z >> 4, h = z & 15;
    const float* Aatt = g_scores + (size_t)z * SEQ * SEQ;                  // [896,896]
    const float* V = g_qkv + (size_t)b * SEQ * 3072 + 2048 + h * 64;       // V[k][d] at k*3072+d
    float* C = g_ctx + (size_t)b * SEQ * DMODEL + h * 64;                  // O[m][d] at m*1024+d
    const int m0 = blockIdx.x * 64;
    const int tid = threadIdx.x;
    const int tx = tid & 15, ty = tid >> 4;
    const int ar = tid >> 2, ak = (tid & 3) * 4;
    const int bk = tid >> 4, bn = (tid & 15) * 4;

    unsigned long long acc[2][4];
#pragma unroll
    for (int i = 0; i < 2; i++)
#pragma unroll
        for (int j = 0; j < 4; j++) acc[i][j] = 0ull;

    for (int k0 = 0; k0 < SEQ; k0 += 16) {
        float4 av = *(const float4*)(Aatt + (size_t)(m0 + ar) * SEQ + k0 + ak);
        As[ak + 0][ar] = av.x; As[ak + 1][ar] = av.y; As[ak + 2][ar] = av.z; As[ak + 3][ar] = av.w;
        *(float4*)&Bs[bk][bn] = *(const float4*)(V + (size_t)(k0 + bk) * 3072 + bn);
        __syncthreads();
#pragma unroll
        for (int kk = 0; kk < 16; kk++) {
            unsigned long long a2[2];
            a2[0] = *(const unsigned long long*)&As[kk][ty * 4];
            a2[1] = *(const unsigned long long*)&As[kk][ty * 4 + 2];
            float4 b4 = *(const float4*)&Bs[kk][tx * 4];
            float bf[4] = {b4.x, b4.y, b4.z, b4.w};
#pragma unroll
            for (int j = 0; j < 4; j++) {
                unsigned long long b2 = pack2(bf[j], bf[j]);
                ffma2(acc[0][j], a2[0], b2);
                ffma2(acc[1][j], a2[1], b2);
            }
        }
        __syncthreads();
    }

    const int mbase = m0 + ty * 4, nbase = tx * 4;
#pragma unroll
    for (int i = 0; i < 2; i++)
#pragma unroll
        for (int j = 0; j < 4; j++) {
            float lo, hi; unpack2(acc[i][j], lo, hi);
            C[(size_t)(mbase + 2 * i) * DMODEL + nbase + j] = lo;
            C[(size_t)(mbase + 2 * i + 1) * DMODEL + nbase + j] = hi;
        }
}

// ---------------- residual add + LayerNorm (in-place on g_tgt, add = g_tmp) ----------------
__global__ void add_ln_kernel(const float* __restrict__ gg, const float* __restrict__ bb)
{
    const size_t row = blockIdx.x;
    float* px = g_tgt + row * DMODEL;
    const float* pa = g_tmp + row * DMODEL;
    const int tid = threadIdx.x;
    __shared__ float sred[8];
    float v[4];
    float s = 0.0f;
#pragma unroll
    for (int i = 0; i < 4; i++) {
        int c = tid + i * 256;
        v[i] = px[c] + pa[c];
        s += v[i];
    }
    const float mean = block_sum256(s, sred) * (1.0f / 1024.0f);
    float q = 0.0f;
#pragma unroll
    for (int i = 0; i < 4; i++) { float d = v[i] - mean; q += d * d; }
    const float var = block_sum256(q, sred) * (1.0f / 1024.0f);
    const float inv = rsqrtf(var + 1e-5f);
#pragma unroll
    for (int i = 0; i < 4; i++) {
        int c = tid + i * 256;
        px[c] = (v[i] - mean) * inv * gg[c] + bb[c];
    }
}

// ---------------- final head + MSE loss (single block) ----------------
__global__ void loss_kernel(const float* __restrict__ Wh, const float* __restrict__ bh,
                            const float* __restrict__ y, const float* __restrict__ w,
                            float* __restrict__ out)
{
    const int tid = threadIdx.x;
    __shared__ float sred[8];
    float lsum = 0.0f;
    for (int jz = tid; jz < BATCH * HAM; jz += 256) {
        const int b = jz / HAM, jj = jz % HAM;
        const float* t = g_tgt + ((size_t)b * SEQ + (SEQ - 1)) * DMODEL;
        const float* wr = Wh + (size_t)jj * DMODEL;
        float a0 = 0.f, a1 = 0.f, a2 = 0.f, a3 = 0.f;
        for (int k = 0; k < DMODEL; k += 4) {
            a0 = fmaf(t[k + 0], wr[k + 0], a0);
            a1 = fmaf(t[k + 1], wr[k + 1], a1);
            a2 = fmaf(t[k + 2], wr[k + 2], a2);
            a3 = fmaf(t[k + 3], wr[k + 3], a3);
        }
        const float hat = ((a0 + a1) + (a2 + a3)) + bh[jj];
        const float resid = y[b * HAM + jj] - w[(size_t)b * 2304 + 2160 + jj]; // w[:, -1]
        const float d = hat - resid;
        lsum += d * d;
    }
    const float tot = block_sum256(lsum, sred);
    if (tid == 0) out[0] = tot * (1.0f / (float)(BATCH * HAM));
}

// ---------------- host orchestration ----------------
extern "C" void kernel_launch(void* const* d_in, const int* in_sizes, int n_in,
                              void* d_out, int out_size)
{
    (void)in_sizes; (void)n_in; (void)out_size;
    const float* x      = (const float*)d_in[0];
    const float* w      = (const float*)d_in[1];
    const float* y      = (const float*)d_in[2];
    const float* W_nail = (const float*)d_in[3];
    const float* b_nail = (const float*)d_in[4];
    const float* W_cond = (const float*)d_in[5];
    const float* b_cond = (const float*)d_in[6];
    const float* Wqkv   = (const float*)d_in[7];
    const float* bqkv   = (const float*)d_in[8];
    const float* Wo     = (const float*)d_in[9];
    const float* bo     = (const float*)d_in[10];
    const float* ln1_g  = (const float*)d_in[11];
    const float* ln1_b  = (const float*)d_in[12];
    const float* ln2_g  = (const float*)d_in[13];
    const float* ln2_b  = (const float*)d_in[14];
    const float* W1     = (const float*)d_in[15];
    const float* b1     = (const float*)d_in[16];
    const float* W2     = (const float*)d_in[17];
    const float* b2     = (const float*)d_in[18];
    const float* W_ham  = (const float*)d_in[19];
    const float* b_ham  = (const float*)d_in[20];

    float *tgt_p, *qkv_p, *ctx_p, *tmp_p, *ff_p;
    cudaGetSymbolAddress((void**)&tgt_p, g_tgt);
    cudaGetSymbolAddress((void**)&qkv_p, g_qkv);
    cudaGetSymbolAddress((void**)&ctx_p, g_ctx);
    cudaGetSymbolAddress((void**)&tmp_p, g_tmp);
    cudaGetSymbolAddress((void**)&ff_p,  g_ff);

    embed_kernel<<<MTOT, 256>>>(x, w, W_nail, b_nail, W_cond, b_cond);

    for (int i = 0; i < NLAY; i++) {
        const float* Wqkv_i = Wqkv + (size_t)i * 3 * DMODEL * DMODEL;
        const float* Wo_i   = Wo   + (size_t)i * DMODEL * DMODEL;
        const float* W1_i   = W1   + (size_t)i * FFDIM * DMODEL;
        const float* W2_i   = W2   + (size_t)i * DMODEL * FFDIM;

        // QKV: (7168,1024) @ (3072,1024)^T
        sgemm_tn_kernel<<<dim3(24, 56), 256>>>(tgt_p, DMODEL, Wqkv_i, DMODEL,
                                               qkv_p, 3 * DMODEL, DMODEL,
                                               bqkv + (size_t)i * 3 * DMODEL, 0);
        // scores + mask + softmax + AV
        attn_scores_kernel<<<dim3(7, 7, BATCH * NHEAD), 256>>>(x);
        softmax_kernel<<<BATCH * NHEAD * SEQ, 256>>>();
        attn_av_kernel<<<dim3(14, BATCH * NHEAD), 256>>>();
        // O projection -> g_tmp
        sgemm_tn_kernel<<<dim3(8, 56), 256>>>(ctx_p, DMODEL, Wo_i, DMODEL,
                                              tmp_p, DMODEL, DMODEL,
                                              bo + (size_t)i * DMODEL, 0);
        // LN1 (residual)
        add_ln_kernel<<<MTOT, 256>>>(ln1_g + (size_t)i * DMODEL, ln1_b + (size_t)i * DMODEL);
        // FF1 + GELU -> g_ff
        sgemm_tn_kernel<<<dim3(32, 56), 256>>>(tgt_p, DMODEL, W1_i, DMODEL,
                                               ff_p, FFDIM, DMODEL,
                                               b1 + (size_t)i * FFDIM, 1);
        // FF2 -> g_tmp
        sgemm_tn_kernel<<<dim3(8, 56), 256>>>(ff_p, FFDIM, W2_i, FFDIM,
                                              tmp_p, DMODEL, FFDIM,
                                              b2 + (size_t)i * DMODEL, 0);
        // LN2 (residual)
        add_ln_kernel<<<MTOT, 256>>>(ln2_g + (size_t)i * DMODEL, ln2_b + (size_t)i * DMODEL);
    }

    loss_kernel<<<1, 256>>>(W_ham, b_ham, y, w, (float*)d_out);
}

// round 8
// speedup vs baseline: 1.6859x; 1.6859x over previous
#include <cuda_runtime.h>
#include <cuda_bf16.h>
#include <math.h>
#include <stdint.h>

// ---------------- problem constants ----------------
#define BATCH 8
#define LX    512
#define SEQ   896
#define DMODEL 1024
#define NHEAD 16
#define HDIM  64
#define FFDIM 4096
#define NLAY  4
#define HAM   144
#define MTOT  (BATCH*SEQ)   // 7168 rows

// ---------------- scratch (device globals: allocation-free) ----------------
static __device__ float g_tgt[(size_t)MTOT * DMODEL];
static __device__ float g_qkv[(size_t)MTOT * 3 * DMODEL];
static __device__ float g_scores[(size_t)BATCH * NHEAD * SEQ * SEQ];
static __device__ float g_tmp[(size_t)MTOT * DMODEL];

// bf16 hi/lo activations
static __device__ __nv_bfloat16 g_tgt_h[(size_t)MTOT * DMODEL];
static __device__ __nv_bfloat16 g_tgt_l[(size_t)MTOT * DMODEL];
static __device__ __nv_bfloat16 g_ctx_h[(size_t)MTOT * DMODEL];
static __device__ __nv_bfloat16 g_ctx_l[(size_t)MTOT * DMODEL];
static __device__ __nv_bfloat16 g_ff_h[(size_t)MTOT * FFDIM];
static __device__ __nv_bfloat16 g_ff_l[(size_t)MTOT * FFDIM];

// bf16 hi/lo weights
static __device__ __nv_bfloat16 g_wqkv_h[(size_t)NLAY * 3 * DMODEL * DMODEL];
static __device__ __nv_bfloat16 g_wqkv_l[(size_t)NLAY * 3 * DMODEL * DMODEL];
static __device__ __nv_bfloat16 g_wo_h[(size_t)NLAY * DMODEL * DMODEL];
static __device__ __nv_bfloat16 g_wo_l[(size_t)NLAY * DMODEL * DMODEL];
static __device__ __nv_bfloat16 g_w1_h[(size_t)NLAY * FFDIM * DMODEL];
static __device__ __nv_bfloat16 g_w1_l[(size_t)NLAY * FFDIM * DMODEL];
static __device__ __nv_bfloat16 g_w2_h[(size_t)NLAY * DMODEL * FFDIM];
static __device__ __nv_bfloat16 g_w2_l[(size_t)NLAY * DMODEL * FFDIM];

// ---------------- helpers ----------------
__device__ __forceinline__ float neg_inf_f() { return __int_as_float(0xff800000); }
__device__ __forceinline__ unsigned long long pack2(float lo, float hi) {
    unsigned long long r;
    asm("mov.b64 %0, {%1, %2};" : "=l"(r) : "f"(lo), "f"(hi));
    return r;
}
__device__ __forceinline__ void unpack2(unsigned long long v, float& lo, float& hi) {
    asm("mov.b64 {%0, %1}, %2;" : "=f"(lo), "=f"(hi) : "l"(v));
}
__device__ __forceinline__ void ffma2(unsigned long long& d, unsigned long long a, unsigned long long b) {
    asm("fma.rn.f32x2 %0, %1, %2, %0;" : "+l"(d) : "l"(a), "l"(b));
}
__device__ __forceinline__ float gelu_exact(float v) {
    return 0.5f * v * (1.0f + erff(v * 0.70710678118654752f));
}
__device__ __forceinline__ void split_bf16(float v, __nv_bfloat16& h, __nv_bfloat16& l) {
    h = __float2bfloat16(v);
    l = __float2bfloat16(v - __bfloat162float(h));
}
__device__ __forceinline__ float block_sum256(float val, float* sred) {
#pragma unroll
    for (int o = 16; o > 0; o >>= 1) val += __shfl_xor_sync(0xffffffffu, val, o);
    if ((threadIdx.x & 31) == 0) sred[threadIdx.x >> 5] = val;
    __syncthreads();
    float t = sred[0];
#pragma unroll
    for (int i = 1; i < 8; i++) t += sred[i];
    __syncthreads();
    return t;
}
__device__ __forceinline__ float block_max256(float val, float* sred) {
#pragma unroll
    for (int o = 16; o > 0; o >>= 1) val = fmaxf(val, __shfl_xor_sync(0xffffffffu, val, o));
    if ((threadIdx.x & 31) == 0) sred[threadIdx.x >> 5] = val;
    __syncthreads();
    float t = sred[0];
#pragma unroll
    for (int i = 1; i < 8; i++) t = fmaxf(t, sred[i]);
    __syncthreads();
    return t;
}

// bf16 mma: D(16x8,f32) += A(16x16,bf16 row) * B(16x8,bf16 col)
__device__ __forceinline__ void mma16816(float* c, const uint32_t* a, const uint32_t* b) {
    asm volatile(
        "mma.sync.aligned.m16n8k16.row.col.f32.bf16.bf16.f32 "
        "{%0,%1,%2,%3}, {%4,%5,%6,%7}, {%8,%9}, {%0,%1,%2,%3};"
        : "+f"(c[0]), "+f"(c[1]), "+f"(c[2]), "+f"(c[3])
        : "r"(a[0]), "r"(a[1]), "r"(a[2]), "r"(a[3]), "r"(b[0]), "r"(b[1]));
}

// ---------------- weight/activation fp32 -> bf16 hi/lo split ----------------
__global__ void split_kernel(const float* __restrict__ src, __nv_bfloat16* __restrict__ hi,
                             __nv_bfloat16* __restrict__ lo, int n4)
{
    int i = blockIdx.x * blockDim.x + threadIdx.x;
    if (i >= n4) return;
    float4 v = ((const float4*)src)[i];
    union { __nv_bfloat16 b[4]; uint2 u; } H, L;
    split_bf16(v.x, H.b[0], L.b[0]);
    split_bf16(v.y, H.b[1], L.b[1]);
    split_bf16(v.z, H.b[2], L.b[2]);
    split_bf16(v.w, H.b[3], L.b[3]);
    ((uint2*)hi)[i] = H.u;
    ((uint2*)lo)[i] = L.u;
}

// ---------------- HMMA GEMM: C[M,N] = (Ah+Al)[M,K] * (Bh+Bl)[N,K]^T + bias ----------------
// 128x128 tile, BK=16, 256 threads (8 warps in 2x4), 64x32 per warp.
// hi*hi + hi*lo + lo*hi (3 HMMA passes) -> fp32-class accuracy.
#define SMS 24   // smem row stride in bf16 (48B) -> conflict-free fragment reads

__global__ void __launch_bounds__(256) mma_gemm_kernel(
    const __nv_bfloat16* __restrict__ Ah, const __nv_bfloat16* __restrict__ Al, int lda,
    const __nv_bfloat16* __restrict__ Bh, const __nv_bfloat16* __restrict__ Bl, int ldb,
    float* __restrict__ Cf, __nv_bfloat16* __restrict__ Ch, __nv_bfloat16* __restrict__ Cl,
    int ldc, int K, const float* __restrict__ bias, int act, int outmode)
{
    __shared__ __nv_bfloat16 sm[2][4][128 * SMS];   // 49152 B
    const int tid = threadIdx.x;
    const int wid = tid >> 5, lane = tid & 31;
    const int g = lane >> 2, t2 = (lane & 3) * 2;
    const int wm = (wid & 1) * 64, wn = (wid >> 1) * 32;
    const int m0 = blockIdx.y * 128, n0 = blockIdx.x * 128;

    const int lrow = tid >> 1, lch = (tid & 1) * 8;
    const __nv_bfloat16* gp0 = Ah + (size_t)(m0 + lrow) * lda + lch;
    const __nv_bfloat16* gp1 = Al + (size_t)(m0 + lrow) * lda + lch;
    const __nv_bfloat16* gp2 = Bh + (size_t)(n0 + lrow) * ldb + lch;
    const __nv_bfloat16* gp3 = Bl + (size_t)(n0 + lrow) * ldb + lch;
    const int so = lrow * SMS + lch;

    float acc[4][4][4];
#pragma unroll
    for (int a = 0; a < 4; a++)
#pragma unroll
        for (int b = 0; b < 4; b++)
#pragma unroll
            for (int c = 0; c < 4; c++) acc[a][b][c] = 0.0f;

    // preload stage 0
    *(uint4*)&sm[0][0][so] = *(const uint4*)gp0;
    *(uint4*)&sm[0][1][so] = *(const uint4*)gp1;
    *(uint4*)&sm[0][2][so] = *(const uint4*)gp2;
    *(uint4*)&sm[0][3][so] = *(const uint4*)gp3;
    __syncthreads();

    const int NC = K >> 4;
    for (int kc = 0; kc < NC; kc++) {
        const int s = kc & 1;
        uint4 p0, p1, p2, p3;
        if (kc + 1 < NC) {
            const int ko = (kc + 1) << 4;
            p0 = *(const uint4*)(gp0 + ko);
            p1 = *(const uint4*)(gp1 + ko);
            p2 = *(const uint4*)(gp2 + ko);
            p3 = *(const uint4*)(gp3 + ko);
        }
        const __nv_bfloat16* As_h = sm[s][0];
        const __nv_bfloat16* As_l = sm[s][1];
        const __nv_bfloat16* Bs_h = sm[s][2];
        const __nv_bfloat16* Bs_l = sm[s][3];

        uint32_t bfh[4][2], bfl[4][2];
#pragma unroll
        for (int nf = 0; nf < 4; nf++) {
            const int base = (wn + nf * 8 + g) * SMS + t2;
            bfh[nf][0] = *(const uint32_t*)&Bs_h[base];
            bfh[nf][1] = *(const uint32_t*)&Bs_h[base + 8];
            bfl[nf][0] = *(const uint32_t*)&Bs_l[base];
            bfl[nf][1] = *(const uint32_t*)&Bs_l[base + 8];
        }
        uint32_t af[4][4];
#pragma unroll
        for (int mf = 0; mf < 4; mf++) {
            const int base = (wm + mf * 16 + g) * SMS + t2;
            af[mf][0] = *(const uint32_t*)&As_h[base];
            af[mf][1] = *(const uint32_t*)&As_h[base + 8 * SMS];
            af[mf][2] = *(const uint32_t*)&As_h[base + 8];
            af[mf][3] = *(const uint32_t*)&As_h[base + 8 * SMS + 8];
        }
#pragma unroll
        for (int mf = 0; mf < 4; mf++)
#pragma unroll
            for (int nf = 0; nf < 4; nf++) {
                mma16816(acc[mf][nf], af[mf], bfh[nf]);
                mma16816(acc[mf][nf], af[mf], bfl[nf]);
            }
#pragma unroll
        for (int mf = 0; mf < 4; mf++) {
            const int base = (wm + mf * 16 + g) * SMS + t2;
            af[mf][0] = *(const uint32_t*)&As_l[base];
            af[mf][1] = *(const uint32_t*)&As_l[base + 8 * SMS];
            af[mf][2] = *(const uint32_t*)&As_l[base + 8];
            af[mf][3] = *(const uint32_t*)&As_l[base + 8 * SMS + 8];
        }
#pragma unroll
        for (int mf = 0; mf < 4; mf++)
#pragma unroll
            for (int nf = 0; nf < 4; nf++)
                mma16816(acc[mf][nf], af[mf], bfh[nf]);

        if (kc + 1 < NC) {
            const int sn = s ^ 1;
            *(uint4*)&sm[sn][0][so] = p0;
            *(uint4*)&sm[sn][1][so] = p1;
            *(uint4*)&sm[sn][2][so] = p2;
            *(uint4*)&sm[sn][3][so] = p3;
        }
        __syncthreads();
    }

    // epilogue: bias (+GELU) and store
    const size_t rbase = (size_t)(m0 + wm + g);
#pragma unroll
    for (int mf = 0; mf < 4; mf++) {
        const size_t r0 = rbase + mf * 16;
#pragma unroll
        for (int nf = 0; nf < 4; nf++) {
            const int c = n0 + wn + nf * 8 + t2;
            const float bj0 = bias[c], bj1 = bias[c + 1];
            float v00 = acc[mf][nf][0] + bj0;
            float v01 = acc[mf][nf][1] + bj1;
            float v10 = acc[mf][nf][2] + bj0;
            float v11 = acc[mf][nf][3] + bj1;
            if (act) {
                v00 = gelu_exact(v00); v01 = gelu_exact(v01);
                v10 = gelu_exact(v10); v11 = gelu_exact(v11);
            }
            if (outmode == 0) {
                float2 u0 = make_float2(v00, v01);
                float2 u1 = make_float2(v10, v11);
                *(float2*)&Cf[r0 * ldc + c] = u0;
                *(float2*)&Cf[(r0 + 8) * ldc + c] = u1;
            } else {
                __nv_bfloat16 h0, l0, h1, l1;
                split_bf16(v00, h0, l0); split_bf16(v01, h1, l1);
                __nv_bfloat162 hh; hh.x = h0; hh.y = h1;
                __nv_bfloat162 ll; ll.x = l0; ll.y = l1;
                *(__nv_bfloat162*)&Ch[r0 * ldc + c] = hh;
                *(__nv_bfloat162*)&Cl[r0 * ldc + c] = ll;
                split_bf16(v10, h0, l0); split_bf16(v11, h1, l1);
                hh.x = h0; hh.y = h1; ll.x = l0; ll.y = l1;
                *(__nv_bfloat162*)&Ch[(r0 + 8) * ldc + c] = hh;
                *(__nv_bfloat162*)&Cl[(r0 + 8) * ldc + c] = ll;
            }
        }
    }
}

// ---------------- embed: tgt = [xx | ww] + PE (fp32 + bf16 hi/lo) ----------------
__global__ void embed_kernel(const float* __restrict__ x, const float* __restrict__ w,
                             const float* __restrict__ Wn, const float* __restrict__ bn,
                             const float* __restrict__ Wc, const float* __restrict__ bc)
{
    const int row = blockIdx.x;
    const int b = row / SEQ, s = row % SEQ;
    const int tid = threadIdx.x;
    const float rinv = rsqrtf(1.0001f);
    const float pefac = -6.90775527898213705f / 1024.0f;
    __shared__ float feat[64];
    __shared__ float tpos_sh;

    if (s < LX) {
        if (tid < 64) {
            float v = x[((size_t)b * LX + s) * 64 + tid];
            if (v != v) v = 0.0f;
            if (tid == 0) tpos_sh = v;
            if (tid >= 1) {
                float u = v * rinv;
                feat[tid - 1] = fminf(fmaxf(u, -5.0f), 5.0f);
            }
        }
        __syncthreads();
        const float t = tpos_sh;
        for (int d = tid; d < DMODEL; d += 256) {
            const float* wr = Wn + (size_t)d * 63;
            float acc = bn[d];
#pragma unroll
            for (int j = 0; j < 63; j++) acc = fmaf(feat[j], wr[j], acc);
            float divf = expf((float)(d >> 1) * pefac);
            float ang = t * divf;
            acc += (d & 1) ? cosf(ang) : sinf(ang);
            const size_t idx = (size_t)row * DMODEL + d;
            g_tgt[idx] = acc;
            __nv_bfloat16 h, l; split_bf16(acc, h, l);
            g_tgt_h[idx] = h; g_tgt_l[idx] = l;
        }
    } else {
        const int j = s - LX;
        if (tid < 6) {
            float v = w[(size_t)b * 2304 + (size_t)j * 6 + tid];
            if (v != v) v = 0.0f;
            float u = v * rinv;
            feat[tid] = fminf(fmaxf(u, -5.0f), 5.0f);
        }
        __syncthreads();
        const float pos = (float)s;
        for (int d = tid; d < DMODEL; d += 256) {
            const float* wr = Wc + (size_t)d * 6;
            float acc = bc[d];
#pragma unroll
            for (int jj = 0; jj < 6; jj++) acc = fmaf(feat[jj], wr[jj], acc);
            float divf = expf((float)(d >> 1) * pefac);
            float ang = pos * divf;
            acc += (d & 1) ? cosf(ang) : sinf(ang);
            const size_t idx = (size_t)row * DMODEL + d;
            g_tgt[idx] = acc;
            __nv_bfloat16 h, l; split_bf16(acc, h, l);
            g_tgt_h[idx] = h; g_tgt_l[idx] = l;
        }
    }
}

// ---------------- attention scores (fp32 ffma2): S = Q K^T / 8, masked ----------------
__global__ void __launch_bounds__(256, 2) attn_scores_kernel(const float* __restrict__ x)
{
    __shared__ __align__(16) float As[8][128];
    __shared__ __align__(16) float Bs[8][128];
    __shared__ bool colnan_s[128];
    const int z = blockIdx.z;
    const int b = z >> 4, h = z & 15;
    const float* A  = g_qkv + (size_t)b * SEQ * 3072 + h * 64;
    const float* Bw = A + 1024;
    float* C = g_scores + (size_t)z * SEQ * SEQ;
    const int tid = threadIdx.x;
    const int tx = tid & 15, ty = tid >> 4;
    const int m0 = blockIdx.y * 128, n0 = blockIdx.x * 128;
    const int lr = tid >> 1, lk = (tid & 1) * 4;

    if (tid < 128) {
        int n = n0 + tid;
        bool cn = false;
        if (n < LX) { float vv = x[((size_t)b * LX + n) * 64]; cn = (vv != vv); }
        colnan_s[tid] = cn;
    }

    const float* Ap = A + (size_t)(m0 + lr) * 3072 + lk;
    const float* Bp = Bw + (size_t)(n0 + lr) * 3072 + lk;
    unsigned long long acc[4][8];
#pragma unroll
    for (int i = 0; i < 4; i++)
#pragma unroll
        for (int j = 0; j < 8; j++) acc[i][j] = 0ull;

    for (int k0 = 0; k0 < 64; k0 += 8) {
        float4 av = *(const float4*)(Ap + k0);
        float4 bv = *(const float4*)(Bp + k0);
        As[lk + 0][lr] = av.x; As[lk + 1][lr] = av.y; As[lk + 2][lr] = av.z; As[lk + 3][lr] = av.w;
        Bs[lk + 0][lr] = bv.x; Bs[lk + 1][lr] = bv.y; Bs[lk + 2][lr] = bv.z; Bs[lk + 3][lr] = bv.w;
        __syncthreads();
#pragma unroll
        for (int kk = 0; kk < 8; kk++) {
            unsigned long long a2[4];
#pragma unroll
            for (int i = 0; i < 4; i++)
                a2[i] = *(const unsigned long long*)&As[kk][ty * 8 + 2 * i];
            float4 b0 = *(const float4*)&Bs[kk][tx * 8];
            float4 b1 = *(const float4*)&Bs[kk][tx * 8 + 4];
            float bf[8] = {b0.x, b0.y, b0.z, b0.w, b1.x, b1.y, b1.z, b1.w};
#pragma unroll
            for (int j = 0; j < 8; j++) {
                unsigned long long b2 = pack2(bf[j], bf[j]);
#pragma unroll
                for (int i = 0; i < 4; i++) ffma2(acc[i][j], a2[i], b2);
            }
        }
        __syncthreads();
    }

    const int mbase = m0 + ty * 8;
    const int nbase = n0 + tx * 8;
    const float NI = neg_inf_f();
#pragma unroll
    for (int j = 0; j < 8; j++) {
        const int n = nbase + j;
        const bool cn = colnan_s[tx * 8 + j];
#pragma unroll
        for (int i = 0; i < 4; i++) {
            float lo, hi; unpack2(acc[i][j], lo, hi);
            const int mlo = mbase + 2 * i, mhi = mlo + 1;
            bool mask_lo = (n < LX) ? cn : (n > mlo);
            bool mask_hi = (n < LX) ? cn : (n > mhi);
            C[(size_t)mlo * SEQ + n] = mask_lo ? NI : lo * 0.125f;
            C[(size_t)mhi * SEQ + n] = mask_hi ? NI : hi * 0.125f;
        }
    }
}

// ---------------- softmax over rows (len 896) ----------------
__global__ void softmax_kernel()
{
    const size_t row = blockIdx.x;
    float* p = g_scores + row * SEQ;
    const int tid = threadIdx.x;
    __shared__ float sred[8];
    float v[4];
    float mx = neg_inf_f();
#pragma unroll
    for (int i = 0; i < 4; i++) {
        int c = tid + i * 256;
        v[i] = (c < SEQ) ? p[c] : neg_inf_f();
        mx = fmaxf(mx, v[i]);
    }
    mx = block_max256(mx, sred);
    float s = 0.0f;
#pragma unroll
    for (int i = 0; i < 4; i++) { v[i] = expf(v[i] - mx); s += v[i]; }
    s = block_sum256(s, sred);
    const float inv = 1.0f / s;
#pragma unroll
    for (int i = 0; i < 4; i++) {
        int c = tid + i * 256;
        if (c < SEQ) p[c] = v[i] * inv;
    }
}

// ---------------- attn @ V: writes context directly as bf16 hi/lo ----------------
__global__ void __launch_bounds__(256) attn_av_kernel()
{
    __shared__ __align__(16) float As[16][64];
    __shared__ __align__(16) float Bs[16][64];
    const int z = blockIdx.y;
    const int b = z >> 4, h = z & 15;
    const float* Aatt = g_scores + (size_t)z * SEQ * SEQ;
    const float* V = g_qkv + (size_t)b * SEQ * 3072 + 2048 + h * 64;
    __nv_bfloat16* Ch = g_ctx_h + (size_t)b * SEQ * DMODEL + h * 64;
    __nv_bfloat16* Cl = g_ctx_l + (size_t)b * SEQ * DMODEL + h * 64;
    const int m0 = blockIdx.x * 64;
    const int tid = threadIdx.x;
    const int tx = tid & 15, ty = tid >> 4;
    const int ar = tid >> 2, ak = (tid & 3) * 4;
    const int bk = tid >> 4, bn = (tid & 15) * 4;

    unsigned long long acc[2][4];
#pragma unroll
    for (int i = 0; i < 2; i++)
#pragma unroll
        for (int j = 0; j < 4; j++) acc[i][j] = 0ull;

    for (int k0 = 0; k0 < SEQ; k0 += 16) {
        float4 av = *(const float4*)(Aatt + (size_t)(m0 + ar) * SEQ + k0 + ak);
        As[ak + 0][ar] = av.x; As[ak + 1][ar] = av.y; As[ak + 2][ar] = av.z; As[ak + 3][ar] = av.w;
        *(float4*)&Bs[bk][bn] = *(const float4*)(V + (size_t)(k0 + bk) * 3072 + bn);
        __syncthreads();
#pragma unroll
        for (int kk = 0; kk < 16; kk++) {
            unsigned long long a2[2];
            a2[0] = *(const unsigned long long*)&As[kk][ty * 4];
            a2[1] = *(const unsigned long long*)&As[kk][ty * 4 + 2];
            float4 b4 = *(const float4*)&Bs[kk][tx * 4];
            float bf[4] = {b4.x, b4.y, b4.z, b4.w};
#pragma unroll
            for (int j = 0; j < 4; j++) {
                unsigned long long b2 = pack2(bf[j], bf[j]);
                ffma2(acc[0][j], a2[0], b2);
                ffma2(acc[1][j], a2[1], b2);
            }
        }
        __syncthreads();
    }

    const int mbase = m0 + ty * 4, nbase = tx * 4;
#pragma unroll
    for (int i = 0; i < 2; i++)
#pragma unroll
        for (int j = 0; j < 4; j++) {
            float lo, hi; unpack2(acc[i][j], lo, hi);
            __nv_bfloat16 h0, l0, h1, l1;
            split_bf16(lo, h0, l0);
            split_bf16(hi, h1, l1);
            Ch[(size_t)(mbase + 2 * i) * DMODEL + nbase + j] = h0;
            Cl[(size_t)(mbase + 2 * i) * DMODEL + nbase + j] = l0;
            Ch[(size_t)(mbase + 2 * i + 1) * DMODEL + nbase + j] = h1;
            Cl[(size_t)(mbase + 2 * i + 1) * DMODEL + nbase + j] = l1;
        }
}

// ---------------- residual add + LayerNorm (fp32 + bf16 hi/lo outputs) ----------------
__global__ void add_ln_kernel(const float* __restrict__ gg, const float* __restrict__ bb)
{
    const size_t row = blockIdx.x;
    float* px = g_tgt + row * DMODEL;
    const float* pa = g_tmp + row * DMODEL;
    const int tid = threadIdx.x;
    __shared__ float sred[8];
    float v[4];
    float s = 0.0f;
#pragma unroll
    for (int i = 0; i < 4; i++) {
        int c = tid + i * 256;
        v[i] = px[c] + pa[c];
        s += v[i];
    }
    const float mean = block_sum256(s, sred) * (1.0f / 1024.0f);
    float q = 0.0f;
#pragma unroll
    for (int i = 0; i < 4; i++) { float d = v[i] - mean; q += d * d; }
    const float var = block_sum256(q, sred) * (1.0f / 1024.0f);
    const float inv = rsqrtf(var + 1e-5f);
#pragma unroll
    for (int i = 0; i < 4; i++) {
        int c = tid + i * 256;
        float o = (v[i] - mean) * inv * gg[c] + bb[c];
        px[c] = o;
        __nv_bfloat16 h, l; split_bf16(o, h, l);
        g_tgt_h[row * DMODEL + c] = h;
        g_tgt_l[row * DMODEL + c] = l;
    }
}

// ---------------- final head + MSE loss (single block) ----------------
__global__ void loss_kernel(const float* __restrict__ Wh, const float* __restrict__ bh,
                            const float* __restrict__ y, const float* __restrict__ w,
                            float* __restrict__ out)
{
    const int tid = threadIdx.x;
    __shared__ float sred[8];
    float lsum = 0.0f;
    for (int jz = tid; jz < BATCH * HAM; jz += 256) {
        const int b = jz / HAM, jj = jz % HAM;
        const float* t = g_tgt + ((size_t)b * SEQ + (SEQ - 1)) * DMODEL;
        const float* wr = Wh + (size_t)jj * DMODEL;
        float a0 = 0.f, a1 = 0.f, a2 = 0.f, a3 = 0.f;
        for (int k = 0; k < DMODEL; k += 4) {
            a0 = fmaf(t[k + 0], wr[k + 0], a0);
            a1 = fmaf(t[k + 1], wr[k + 1], a1);
            a2 = fmaf(t[k + 2], wr[k + 2], a2);
            a3 = fmaf(t[k + 3], wr[k + 3], a3);
        }
        const float hat = ((a0 + a1) + (a2 + a3)) + bh[jj];
        const float resid = y[b * HAM + jj] - w[(size_t)b * 2304 + 2160 + jj];
        const float d = hat - resid;
        lsum += d * d;
    }
    const float tot = block_sum256(lsum, sred);
    if (tid == 0) out[0] = tot * (1.0f / (float)(BATCH * HAM));
}

// ---------------- host orchestration ----------------
extern "C" void kernel_launch(void* const* d_in, const int* in_sizes, int n_in,
                              void* d_out, int out_size)
{
    (void)in_sizes; (void)n_in; (void)out_size;
    const float* x      = (const float*)d_in[0];
    const float* w      = (const float*)d_in[1];
    const float* y      = (const float*)d_in[2];
    const float* W_nail = (const float*)d_in[3];
    const float* b_nail = (const float*)d_in[4];
    const float* W_cond = (const float*)d_in[5];
    const float* b_cond = (const float*)d_in[6];
    const float* Wqkv   = (const float*)d_in[7];
    const float* bqkv   = (const float*)d_in[8];
    const float* Wo     = (const float*)d_in[9];
    const float* bo     = (const float*)d_in[10];
    const float* ln1_g  = (const float*)d_in[11];
    const float* ln1_b  = (const float*)d_in[12];
    const float* ln2_g  = (const float*)d_in[13];
    const float* ln2_b  = (const float*)d_in[14];
    const float* W1     = (const float*)d_in[15];
    const float* b1     = (const float*)d_in[16];
    const float* W2     = (const float*)d_in[17];
    const float* b2     = (const float*)d_in[18];
    const float* W_ham  = (const float*)d_in[19];
    const float* b_ham  = (const float*)d_in[20];

    float *qkv_p, *tmp_p;
    __nv_bfloat16 *tgth_p, *tgtl_p, *ctxh_p, *ctxl_p, *ffh_p, *ffl_p;
    __nv_bfloat16 *wqkvh_p, *wqkvl_p, *woh_p, *wol_p, *w1h_p, *w1l_p, *w2h_p, *w2l_p;
    cudaGetSymbolAddress((void**)&qkv_p, g_qkv);
    cudaGetSymbolAddress((void**)&tmp_p, g_tmp);
    cudaGetSymbolAddress((void**)&tgth_p, g_tgt_h);
    cudaGetSymbolAddress((void**)&tgtl_p, g_tgt_l);
    cudaGetSymbolAddress((void**)&ctxh_p, g_ctx_h);
    cudaGetSymbolAddress((void**)&ctxl_p, g_ctx_l);
    cudaGetSymbolAddress((void**)&ffh_p, g_ff_h);
    cudaGetSymbolAddress((void**)&ffl_p, g_ff_l);
    cudaGetSymbolAddress((void**)&wqkvh_p, g_wqkv_h);
    cudaGetSymbolAddress((void**)&wqkvl_p, g_wqkv_l);
    cudaGetSymbolAddress((void**)&woh_p, g_wo_h);
    cudaGetSymbolAddress((void**)&wol_p, g_wo_l);
    cudaGetSymbolAddress((void**)&w1h_p, g_w1_h);
    cudaGetSymbolAddress((void**)&w1l_p, g_w1_l);
    cudaGetSymbolAddress((void**)&w2h_p, g_w2_h);
    cudaGetSymbolAddress((void**)&w2l_p, g_w2_l);

    // weight splits (memory-bound, ~100us)
    {
        int n4;
        n4 = NLAY * 3 * DMODEL * DMODEL / 4;
        split_kernel<<<(n4 + 255) / 256, 256>>>(Wqkv, wqkvh_p, wqkvl_p, n4);
        n4 = NLAY * DMODEL * DMODEL / 4;
        split_kernel<<<(n4 + 255) / 256, 256>>>(Wo, woh_p, wol_p, n4);
        n4 = NLAY * FFDIM * DMODEL / 4;
        split_kernel<<<(n4 + 255) / 256, 256>>>(W1, w1h_p, w1l_p, n4);
        n4 = NLAY * DMODEL * FFDIM / 4;
        split_kernel<<<(n4 + 255) / 256, 256>>>(W2, w2h_p, w2l_p, n4);
    }

    embed_kernel<<<MTOT, 256>>>(x, w, W_nail, b_nail, W_cond, b_cond);

    for (int i = 0; i < NLAY; i++) {
        __nv_bfloat16* Wqkv_h = wqkvh_p + (size_t)i * 3 * DMODEL * DMODEL;
        __nv_bfloat16* Wqkv_l = wqkvl_p + (size_t)i * 3 * DMODEL * DMODEL;
        __nv_bfloat16* Wo_h   = woh_p + (size_t)i * DMODEL * DMODEL;
        __nv_bfloat16* Wo_l   = wol_p + (size_t)i * DMODEL * DMODEL;
        __nv_bfloat16* W1_h   = w1h_p + (size_t)i * FFDIM * DMODEL;
        __nv_bfloat16* W1_l   = w1l_p + (size_t)i * FFDIM * DMODEL;
        __nv_bfloat16* W2_h   = w2h_p + (size_t)i * DMODEL * FFDIM;
        __nv_bfloat16* W2_l   = w2l_p + (size_t)i * DMODEL * FFDIM;

        // QKV: (7168,1024) @ (3072,1024)^T -> g_qkv fp32
        mma_gemm_kernel<<<dim3(24, 56), 256>>>(
            tgth_p, tgtl_p, DMODEL, Wqkv_h, Wqkv_l, DMODEL,
            qkv_p, (__nv_bfloat16*)0, (__nv_bfloat16*)0, 3 * DMODEL, DMODEL,
            bqkv + (size_t)i * 3 * DMODEL, 0, 0);
        // attention (fp32)
        attn_scores_kernel<<<dim3(7, 7, BATCH * NHEAD), 256>>>(x);
        softmax_kernel<<<BATCH * NHEAD * SEQ, 256>>>();
        attn_av_kernel<<<dim3(14, BATCH * NHEAD), 256>>>();
        // O projection -> g_tmp fp32
        mma_gemm_kernel<<<dim3(8, 56), 256>>>(
            ctxh_p, ctxl_p, DMODEL, Wo_h, Wo_l, DMODEL,
            tmp_p, (__nv_bfloat16*)0, (__nv_bfloat16*)0, DMODEL, DMODEL,
            bo + (size_t)i * DMODEL, 0, 0);
        add_ln_kernel<<<MTOT, 256>>>(ln1_g + (size_t)i * DMODEL, ln1_b + (size_t)i * DMODEL);
        // FF1 + GELU -> bf16 hi/lo ff buffers
        mma_gemm_kernel<<<dim3(32, 56), 256>>>(
            tgth_p, tgtl_p, DMODEL, W1_h, W1_l, DMODEL,
            (float*)0, ffh_p, ffl_p, FFDIM, DMODEL,
            b1 + (size_t)i * FFDIM, 1, 1);
        // FF2 -> g_tmp fp32
        mma_gemm_kernel<<<dim3(8, 56), 256>>>(
            ffh_p, ffl_p, FFDIM, W2_h, W2_l, FFDIM,
            tmp_p, (__nv_bfloat16*)0, (__nv_bfloat16*)0, DMODEL, FFDIM,
            b2 + (size_t)i * DMODEL, 0, 0);
        add_ln_kernel<<<MTOT, 256>>>(ln2_g + (size_t)i * DMODEL, ln2_b + (size_t)i * DMODEL);
    }

    loss_kernel<<<1, 256>>>(W_ham, b_ham, y, w, (float*)d_out);
}

// round 9
// speedup vs baseline: 2.1431x; 1.2712x over previous
#include <cuda_runtime.h>
#include <cuda_bf16.h>
#include <math.h>
#include <stdint.h>

// ---------------- problem constants ----------------
#define BATCH 8
#define LX    512
#define SEQ   896
#define DMODEL 1024
#define NHEAD 16
#define HDIM  64
#define FFDIM 4096
#define NLAY  4
#define HAM   144
#define MTOT  (BATCH*SEQ)   // 7168 rows

// ---------------- scratch (device globals: allocation-free) ----------------
static __device__ float g_tgt[(size_t)MTOT * DMODEL];
static __device__ float g_tmp[(size_t)MTOT * DMODEL];

// bf16 hi/lo activations
static __device__ __nv_bfloat16 g_tgt_h[(size_t)MTOT * DMODEL];
static __device__ __nv_bfloat16 g_tgt_l[(size_t)MTOT * DMODEL];
static __device__ __nv_bfloat16 g_qkv_h[(size_t)MTOT * 3 * DMODEL];
static __device__ __nv_bfloat16 g_qkv_l[(size_t)MTOT * 3 * DMODEL];
static __device__ __nv_bfloat16 g_ctx_h[(size_t)MTOT * DMODEL];
static __device__ __nv_bfloat16 g_ctx_l[(size_t)MTOT * DMODEL];
static __device__ __nv_bfloat16 g_ff_h[(size_t)MTOT * FFDIM];
static __device__ __nv_bfloat16 g_ff_l[(size_t)MTOT * FFDIM];

// bf16 hi/lo weights
static __device__ __nv_bfloat16 g_wqkv_h[(size_t)NLAY * 3 * DMODEL * DMODEL];
static __device__ __nv_bfloat16 g_wqkv_l[(size_t)NLAY * 3 * DMODEL * DMODEL];
static __device__ __nv_bfloat16 g_wo_h[(size_t)NLAY * DMODEL * DMODEL];
static __device__ __nv_bfloat16 g_wo_l[(size_t)NLAY * DMODEL * DMODEL];
static __device__ __nv_bfloat16 g_w1_h[(size_t)NLAY * FFDIM * DMODEL];
static __device__ __nv_bfloat16 g_w1_l[(size_t)NLAY * FFDIM * DMODEL];
static __device__ __nv_bfloat16 g_w2_h[(size_t)NLAY * DMODEL * FFDIM];
static __device__ __nv_bfloat16 g_w2_l[(size_t)NLAY * DMODEL * FFDIM];

// ---------------- helpers ----------------
#define NEG_INF __int_as_float(0xff800000)

__device__ __forceinline__ float gelu_exact(float v) {
    return 0.5f * v * (1.0f + erff(v * 0.70710678118654752f));
}
__device__ __forceinline__ void split_bf16(float v, __nv_bfloat16& h, __nv_bfloat16& l) {
    h = __float2bfloat16(v);
    l = __float2bfloat16(v - __bfloat162float(h));
}
__device__ __forceinline__ uint32_t bf2u(__nv_bfloat16 a, __nv_bfloat16 b) {
    __nv_bfloat162 t; t.x = a; t.y = b;
    return *reinterpret_cast<uint32_t*>(&t);
}
__device__ __forceinline__ float block_sum256(float val, float* sred) {
#pragma unroll
    for (int o = 16; o > 0; o >>= 1) val += __shfl_xor_sync(0xffffffffu, val, o);
    if ((threadIdx.x & 31) == 0) sred[threadIdx.x >> 5] = val;
    __syncthreads();
    float t = sred[0];
#pragma unroll
    for (int i = 1; i < 8; i++) t += sred[i];
    __syncthreads();
    return t;
}

// bf16 mma: D(16x8,f32) += A(16x16,bf16 row) * B(16x8,bf16 col)
__device__ __forceinline__ void mma16816(float* c, const uint32_t* a, const uint32_t* b) {
    asm volatile(
        "mma.sync.aligned.m16n8k16.row.col.f32.bf16.bf16.f32 "
        "{%0,%1,%2,%3}, {%4,%5,%6,%7}, {%8,%9}, {%0,%1,%2,%3};"
        : "+f"(c[0]), "+f"(c[1]), "+f"(c[2]), "+f"(c[3])
        : "r"(a[0]), "r"(a[1]), "r"(a[2]), "r"(a[3]), "r"(b[0]), "r"(b[1]));
}

__device__ __forceinline__ uint32_t smem_u32(const void* p) {
    uint32_t a;
    asm("{ .reg .u64 t; cvta.to.shared.u64 t, %1; cvt.u32.u64 %0, t; }" : "=r"(a) : "l"(p));
    return a;
}
__device__ __forceinline__ void cp16(uint32_t dst, const void* src) {
    asm volatile("cp.async.cg.shared.global [%0], [%1], 16;" :: "r"(dst), "l"(src));
}
#define CP_COMMIT() asm volatile("cp.async.commit_group;" ::: "memory")
#define CP_WAIT0()  asm volatile("cp.async.wait_group 0;" ::: "memory")

// ---------------- weight/activation fp32 -> bf16 hi/lo split ----------------
__global__ void split_kernel(const float* __restrict__ src, __nv_bfloat16* __restrict__ hi,
                             __nv_bfloat16* __restrict__ lo, int n4)
{
    int i = blockIdx.x * blockDim.x + threadIdx.x;
    if (i >= n4) return;
    float4 v = ((const float4*)src)[i];
    union { __nv_bfloat16 b[4]; uint2 u; } H, L;
    split_bf16(v.x, H.b[0], L.b[0]);
    split_bf16(v.y, H.b[1], L.b[1]);
    split_bf16(v.z, H.b[2], L.b[2]);
    split_bf16(v.w, H.b[3], L.b[3]);
    ((uint2*)hi)[i] = H.u;
    ((uint2*)lo)[i] = L.u;
}

// ---------------- HMMA GEMM: C[M,N] = (Ah+Al)[M,K]*(Bh+Bl)[N,K]^T + bias ----------------
// Tile 128x256, 8 warps (2x4), warp tile 64x64, BK=16, cp.async double buffer.
// smem per stage (bf16): Ah 128*24, Al 128*24, Bh 256*24, Bl 256*24 = 18432
#define GST 18432
#define GSMEM_BYTES (2 * GST * 2)

__global__ void __launch_bounds__(256) mma_gemm_kernel(
    const __nv_bfloat16* __restrict__ Ah, const __nv_bfloat16* __restrict__ Al, int lda,
    const __nv_bfloat16* __restrict__ Bh, const __nv_bfloat16* __restrict__ Bl, int ldb,
    float* __restrict__ Cf, __nv_bfloat16* __restrict__ Ch, __nv_bfloat16* __restrict__ Cl,
    int ldc, int K, const float* __restrict__ bias, int act, int outmode)
{
    extern __shared__ __nv_bfloat16 gsm[];
    const uint32_t smbase = smem_u32(gsm);
    const int tid = threadIdx.x;
    const int wid = tid >> 5, lane = tid & 31;
    const int g = lane >> 2, t2 = (lane & 3) * 2;
    const int wm = (wid & 1) * 64, wn = (wid >> 1) * 64;
    const int m0 = blockIdx.y * 128, n0 = blockIdx.x * 256;

    // loader mapping
    const int ar = tid >> 1, acg = tid & 1;               // A: 128 rows x 2 col-grps
    const int br0 = tid >> 1, bcg0 = tid & 1;             // B part 0
    const int br1 = (tid + 256) >> 1, bcg1 = tid & 1;     // B part 1

    const __nv_bfloat16* gAh = Ah + (size_t)(m0 + ar) * lda + acg * 8;
    const __nv_bfloat16* gAl = Al + (size_t)(m0 + ar) * lda + acg * 8;
    const __nv_bfloat16* gBh0 = Bh + (size_t)(n0 + br0) * ldb + bcg0 * 8;
    const __nv_bfloat16* gBl0 = Bl + (size_t)(n0 + br0) * ldb + bcg0 * 8;
    const __nv_bfloat16* gBh1 = Bh + (size_t)(n0 + br1) * ldb + bcg1 * 8;
    const __nv_bfloat16* gBl1 = Bl + (size_t)(n0 + br1) * ldb + bcg1 * 8;

    const uint32_t sAh_w = smbase + (ar * 24 + acg * 8) * 2;
    const uint32_t sAl_w = sAh_w + 128 * 24 * 2;
    const uint32_t sBh_w0 = smbase + (2 * 128 * 24 + br0 * 24 + bcg0 * 8) * 2;
    const uint32_t sBl_w0 = sBh_w0 + 256 * 24 * 2;
    const uint32_t sBh_w1 = smbase + (2 * 128 * 24 + br1 * 24 + bcg1 * 8) * 2;
    const uint32_t sBl_w1 = sBh_w1 + 256 * 24 * 2;

    float acc[4][8][4];
#pragma unroll
    for (int a = 0; a < 4; a++)
#pragma unroll
        for (int b = 0; b < 8; b++)
#pragma unroll
            for (int c = 0; c < 4; c++) acc[a][b][c] = 0.0f;

    const int NC = K >> 4;
    // issue stage 0
    {
        cp16(sAh_w, gAh); cp16(sAl_w, gAl);
        cp16(sBh_w0, gBh0); cp16(sBl_w0, gBl0);
        cp16(sBh_w1, gBh1); cp16(sBl_w1, gBl1);
        CP_COMMIT();
    }

    for (int kc = 0; kc < NC; kc++) {
        const int s = kc & 1;
        CP_WAIT0();
        __syncthreads();
        if (kc + 1 < NC) {
            const int ko = (kc + 1) << 4;
            const uint32_t so = (s ^ 1) ? (uint32_t)(GST * 2) : 0u;
            cp16(sAh_w + so, gAh + ko); cp16(sAl_w + so, gAl + ko);
            cp16(sBh_w0 + so, gBh0 + ko); cp16(sBl_w0 + so, gBl0 + ko);
            cp16(sBh_w1 + so, gBh1 + ko); cp16(sBl_w1 + so, gBl1 + ko);
            CP_COMMIT();
        }
        const __nv_bfloat16* st = gsm + s * GST;
        const __nv_bfloat16* pAh = st;
        const __nv_bfloat16* pAl = st + 128 * 24;
        const __nv_bfloat16* pBh = st + 2 * 128 * 24;
        const __nv_bfloat16* pBl = pBh + 256 * 24;

        uint32_t afh[4][4], afl[4][4];
#pragma unroll
        for (int mf = 0; mf < 4; mf++) {
            const int base = (wm + mf * 16 + g) * 24 + t2;
            afh[mf][0] = *(const uint32_t*)&pAh[base];
            afh[mf][1] = *(const uint32_t*)&pAh[base + 8 * 24];
            afh[mf][2] = *(const uint32_t*)&pAh[base + 8];
            afh[mf][3] = *(const uint32_t*)&pAh[base + 8 * 24 + 8];
            afl[mf][0] = *(const uint32_t*)&pAl[base];
            afl[mf][1] = *(const uint32_t*)&pAl[base + 8 * 24];
            afl[mf][2] = *(const uint32_t*)&pAl[base + 8];
            afl[mf][3] = *(const uint32_t*)&pAl[base + 8 * 24 + 8];
        }
#pragma unroll
        for (int nf = 0; nf < 8; nf++) {
            const int bb = (wn + nf * 8 + g) * 24 + t2;
            uint32_t bh2[2], bl2[2];
            bh2[0] = *(const uint32_t*)&pBh[bb];
            bh2[1] = *(const uint32_t*)&pBh[bb + 8];
            bl2[0] = *(const uint32_t*)&pBl[bb];
            bl2[1] = *(const uint32_t*)&pBl[bb + 8];
#pragma unroll
            for (int mf = 0; mf < 4; mf++) {
                mma16816(acc[mf][nf], afh[mf], bh2);
                mma16816(acc[mf][nf], afl[mf], bh2);
                mma16816(acc[mf][nf], afh[mf], bl2);
            }
        }
        __syncthreads();
    }

    // epilogue
#pragma unroll
    for (int mf = 0; mf < 4; mf++) {
        const size_t r0 = (size_t)(m0 + wm + mf * 16 + g);
#pragma unroll
        for (int nf = 0; nf < 8; nf++) {
            const int c = n0 + wn + nf * 8 + t2;
            const float bj0 = bias[c], bj1 = bias[c + 1];
            float v00 = acc[mf][nf][0] + bj0;
            float v01 = acc[mf][nf][1] + bj1;
            float v10 = acc[mf][nf][2] + bj0;
            float v11 = acc[mf][nf][3] + bj1;
            if (act) {
                v00 = gelu_exact(v00); v01 = gelu_exact(v01);
                v10 = gelu_exact(v10); v11 = gelu_exact(v11);
            }
            if (outmode == 0) {
                *(float2*)&Cf[r0 * ldc + c] = make_float2(v00, v01);
                *(float2*)&Cf[(r0 + 8) * ldc + c] = make_float2(v10, v11);
            } else {
                __nv_bfloat16 h0, l0, h1, l1;
                split_bf16(v00, h0, l0); split_bf16(v01, h1, l1);
                *(uint32_t*)&Ch[r0 * ldc + c] = bf2u(h0, h1);
                *(uint32_t*)&Cl[r0 * ldc + c] = bf2u(l0, l1);
                split_bf16(v10, h0, l0); split_bf16(v11, h1, l1);
                *(uint32_t*)&Ch[(r0 + 8) * ldc + c] = bf2u(h0, h1);
                *(uint32_t*)&Cl[(r0 + 8) * ldc + c] = bf2u(l0, l1);
            }
        }
    }
}

// ---------------- flash attention ----------------
// grid (7, 128) = (qblock, b*16+h); 256 threads, warp owns 16 query rows.
// smem: Qh/Ql [128][72], Kh/Kl [128][72], VTh/VTl [64][136]
#define QS 72
#define VTS 136
#define FA_SMEM ((4 * 128 * QS + 2 * 64 * VTS) * 2)

__global__ void __launch_bounds__(256) flash_kernel(const float* __restrict__ x)
{
    extern __shared__ __nv_bfloat16 fsm[];
    __nv_bfloat16* Qh = fsm;
    __nv_bfloat16* Ql = Qh + 128 * QS;
    __nv_bfloat16* Kh = Ql + 128 * QS;
    __nv_bfloat16* Kl = Kh + 128 * QS;
    __nv_bfloat16* VTh = Kl + 128 * QS;
    __nv_bfloat16* VTl = VTh + 64 * VTS;
    __shared__ float cmask[128];

    const int qb = blockIdx.x;
    const int z = blockIdx.y;
    const int b = z >> 4, h = z & 15;
    const int tid = threadIdx.x;
    const int warp = tid >> 5, lane = tid & 31;
    const int g = lane >> 2, t2 = (lane & 3) * 2;
    const size_t rowbase = (size_t)b * SEQ;

    // load Q block (128 rows x 64 dims, hi/lo)
#pragma unroll
    for (int i = 0; i < 4; i++) {
        const int idx = tid + i * 256;
        const int r = idx >> 3, gp = idx & 7;
        const size_t goff = (rowbase + qb * 128 + r) * 3072 + h * 64 + gp * 8;
        *(uint4*)&Qh[r * QS + gp * 8] = *(const uint4*)&g_qkv_h[goff];
        *(uint4*)&Ql[r * QS + gp * 8] = *(const uint4*)&g_qkv_l[goff];
    }

    float O[8][4];
#pragma unroll
    for (int a = 0; a < 8; a++)
#pragma unroll
        for (int c = 0; c < 4; c++) O[a][c] = 0.0f;
    float m0r = NEG_INF, m1r = NEG_INF, l0r = 0.0f, l1r = 0.0f;
    const int mt0 = qb * 128 + warp * 16 + g;   // token row for c0/c1; c2/c3 = +8

    for (int kb = 0; kb < 7; kb++) {
        if (kb >= 4 && kb > qb) break;   // fully causal-masked from here on

        // load K block + V^T block
#pragma unroll
        for (int i = 0; i < 4; i++) {
            const int idx = tid + i * 256;
            const int r = idx >> 3, gp = idx & 7;
            const size_t base = (rowbase + kb * 128 + r) * 3072 + h * 64 + gp * 8;
            *(uint4*)&Kh[r * QS + gp * 8] = *(const uint4*)&g_qkv_h[base + 1024];
            *(uint4*)&Kl[r * QS + gp * 8] = *(const uint4*)&g_qkv_l[base + 1024];
            union { uint4 v; __nv_bfloat16 e[8]; } vh, vl;
            vh.v = *(const uint4*)&g_qkv_h[base + 2048];
            vl.v = *(const uint4*)&g_qkv_l[base + 2048];
#pragma unroll
            for (int d = 0; d < 8; d++) {
                VTh[(gp * 8 + d) * VTS + r] = vh.e[d];
                VTl[(gp * 8 + d) * VTS + r] = vl.e[d];
            }
        }
        if (tid < 128) {
            const int tok = kb * 128 + tid;
            float cm = 0.0f;
            if (tok < LX) {
                const float vv = x[((size_t)b * LX + tok) * 64];
                if (vv != vv) cm = NEG_INF;
            }
            cmask[tid] = cm;
        }
        __syncthreads();

        // S = Q K^T, 3-pass hi/lo
        float S[16][4];
#pragma unroll
        for (int nf = 0; nf < 16; nf++)
#pragma unroll
            for (int c = 0; c < 4; c++) S[nf][c] = 0.0f;

#pragma unroll
        for (int kc = 0; kc < 4; kc++) {
            const int ab = (warp * 16 + g) * QS + kc * 16 + t2;
            uint32_t ah[4], al[4];
            ah[0] = *(const uint32_t*)&Qh[ab];
            ah[1] = *(const uint32_t*)&Qh[ab + 8 * QS];
            ah[2] = *(const uint32_t*)&Qh[ab + 8];
            ah[3] = *(const uint32_t*)&Qh[ab + 8 * QS + 8];
            al[0] = *(const uint32_t*)&Ql[ab];
            al[1] = *(const uint32_t*)&Ql[ab + 8 * QS];
            al[2] = *(const uint32_t*)&Ql[ab + 8];
            al[3] = *(const uint32_t*)&Ql[ab + 8 * QS + 8];
#pragma unroll
            for (int nf = 0; nf < 16; nf++) {
                const int bb = (nf * 8 + g) * QS + kc * 16 + t2;
                uint32_t bh2[2], bl2[2];
                bh2[0] = *(const uint32_t*)&Kh[bb];
                bh2[1] = *(const uint32_t*)&Kh[bb + 8];
                bl2[0] = *(const uint32_t*)&Kl[bb];
                bl2[1] = *(const uint32_t*)&Kl[bb + 8];
                mma16816(S[nf], ah, bh2);
                mma16816(S[nf], al, bh2);
                mma16816(S[nf], ah, bl2);
            }
        }

        // scale + mask
        const bool xblk = (kb < 4);
        const bool diag = (kb == qb) && (kb >= 4);
#pragma unroll
        for (int nf = 0; nf < 16; nf++) {
            const int c0 = nf * 8 + t2;
            if (xblk) {
                const float cm0 = cmask[c0], cm1 = cmask[c0 + 1];
                S[nf][0] = S[nf][0] * 0.125f + cm0;
                S[nf][1] = S[nf][1] * 0.125f + cm1;
                S[nf][2] = S[nf][2] * 0.125f + cm0;
                S[nf][3] = S[nf][3] * 0.125f + cm1;
            } else if (diag) {
                const int nt0 = kb * 128 + c0;
                S[nf][0] = (nt0     > mt0    ) ? NEG_INF : S[nf][0] * 0.125f;
                S[nf][1] = (nt0 + 1 > mt0    ) ? NEG_INF : S[nf][1] * 0.125f;
                S[nf][2] = (nt0     > mt0 + 8) ? NEG_INF : S[nf][2] * 0.125f;
                S[nf][3] = (nt0 + 1 > mt0 + 8) ? NEG_INF : S[nf][3] * 0.125f;
            } else {
                S[nf][0] *= 0.125f; S[nf][1] *= 0.125f;
                S[nf][2] *= 0.125f; S[nf][3] *= 0.125f;
            }
        }

        // online softmax
        float bm0 = NEG_INF, bm1 = NEG_INF;
#pragma unroll
        for (int nf = 0; nf < 16; nf++) {
            bm0 = fmaxf(bm0, fmaxf(S[nf][0], S[nf][1]));
            bm1 = fmaxf(bm1, fmaxf(S[nf][2], S[nf][3]));
        }
        bm0 = fmaxf(bm0, __shfl_xor_sync(0xffffffffu, bm0, 1));
        bm0 = fmaxf(bm0, __shfl_xor_sync(0xffffffffu, bm0, 2));
        bm1 = fmaxf(bm1, __shfl_xor_sync(0xffffffffu, bm1, 1));
        bm1 = fmaxf(bm1, __shfl_xor_sync(0xffffffffu, bm1, 2));
        const float mn0 = fmaxf(m0r, bm0), mn1 = fmaxf(m1r, bm1);
        const float a0 = __expf(m0r - mn0), a1 = __expf(m1r - mn1);
        m0r = mn0; m1r = mn1;
        float ps0 = 0.0f, ps1 = 0.0f;
#pragma unroll
        for (int nf = 0; nf < 16; nf++) {
            S[nf][0] = __expf(S[nf][0] - mn0);
            S[nf][1] = __expf(S[nf][1] - mn0);
            S[nf][2] = __expf(S[nf][2] - mn1);
            S[nf][3] = __expf(S[nf][3] - mn1);
            ps0 += S[nf][0] + S[nf][1];
            ps1 += S[nf][2] + S[nf][3];
        }
        ps0 += __shfl_xor_sync(0xffffffffu, ps0, 1);
        ps0 += __shfl_xor_sync(0xffffffffu, ps0, 2);
        ps1 += __shfl_xor_sync(0xffffffffu, ps1, 1);
        ps1 += __shfl_xor_sync(0xffffffffu, ps1, 2);
        l0r = l0r * a0 + ps0;
        l1r = l1r * a1 + ps1;
#pragma unroll
        for (int nf = 0; nf < 8; nf++) {
            O[nf][0] *= a0; O[nf][1] *= a0;
            O[nf][2] *= a1; O[nf][3] *= a1;
        }

        // O += P V  (3-pass hi/lo, P from S regs)
#pragma unroll
        for (int kc = 0; kc < 8; kc++) {
            uint32_t ph[4], pl[4];
            {
                __nv_bfloat16 h00, l00, h01, l01;
#pragma unroll
                for (int q = 0; q < 2; q++) {
                    const int nf = 2 * kc + q;
                    split_bf16(S[nf][0], h00, l00);
                    split_bf16(S[nf][1], h01, l01);
                    ph[q * 2 + 0] = bf2u(h00, h01);
                    pl[q * 2 + 0] = bf2u(l00, l01);
                    split_bf16(S[nf][2], h00, l00);
                    split_bf16(S[nf][3], h01, l01);
                    ph[q * 2 + 1] = bf2u(h00, h01);
                    pl[q * 2 + 1] = bf2u(l00, l01);
                }
            }
#pragma unroll
            for (int nf = 0; nf < 8; nf++) {
                const int bb = (nf * 8 + g) * VTS + kc * 16 + t2;
                uint32_t vh2[2], vl2[2];
                vh2[0] = *(const uint32_t*)&VTh[bb];
                vh2[1] = *(const uint32_t*)&VTh[bb + 8];
                vl2[0] = *(const uint32_t*)&VTl[bb];
                vl2[1] = *(const uint32_t*)&VTl[bb + 8];
                mma16816(O[nf], ph, vh2);
                mma16816(O[nf], pl, vh2);
                mma16816(O[nf], ph, vl2);
            }
        }
        __syncthreads();
    }

    // finalize: O /= l, write bf16 hi/lo context
    const float i0 = 1.0f / l0r, i1 = 1.0f / l1r;
    const size_t r0 = rowbase + qb * 128 + warp * 16 + g;
#pragma unroll
    for (int nf = 0; nf < 8; nf++) {
        const int col = h * 64 + nf * 8 + t2;
        float v00 = O[nf][0] * i0, v01 = O[nf][1] * i0;
        float v10 = O[nf][2] * i1, v11 = O[nf][3] * i1;
        __nv_bfloat16 h0, l0, h1, l1;
        split_bf16(v00, h0, l0); split_bf16(v01, h1, l1);
        *(uint32_t*)&g_ctx_h[r0 * DMODEL + col] = bf2u(h0, h1);
        *(uint32_t*)&g_ctx_l[r0 * DMODEL + col] = bf2u(l0, l1);
        split_bf16(v10, h0, l0); split_bf16(v11, h1, l1);
        *(uint32_t*)&g_ctx_h[(r0 + 8) * DMODEL + col] = bf2u(h0, h1);
        *(uint32_t*)&g_ctx_l[(r0 + 8) * DMODEL + col] = bf2u(l0, l1);
    }
}

// ---------------- embed: tgt = [xx | ww] + PE (fp32 + bf16 hi/lo) ----------------
__global__ void embed_kernel(const float* __restrict__ x, const float* __restrict__ w,
                             const float* __restrict__ Wn, const float* __restrict__ bn,
                             const float* __restrict__ Wc, const float* __restrict__ bc)
{
    const int row = blockIdx.x;
    const int b = row / SEQ, s = row % SEQ;
    const int tid = threadIdx.x;
    const float rinv = rsqrtf(1.0001f);
    const float pefac = -6.90775527898213705f / 1024.0f;
    __shared__ float feat[64];
    __shared__ float tpos_sh;

    if (s < LX) {
        if (tid < 64) {
            float v = x[((size_t)b * LX + s) * 64 + tid];
            if (v != v) v = 0.0f;
            if (tid == 0) tpos_sh = v;
            if (tid >= 1) {
                float u = v * rinv;
                feat[tid - 1] = fminf(fmaxf(u, -5.0f), 5.0f);
            }
        }
        __syncthreads();
        const float t = tpos_sh;
        for (int d = tid; d < DMODEL; d += 256) {
            const float* wr = Wn + (size_t)d * 63;
            float acc = bn[d];
#pragma unroll
            for (int j = 0; j < 63; j++) acc = fmaf(feat[j], wr[j], acc);
            float divf = expf((float)(d >> 1) * pefac);
            float ang = t * divf;
            acc += (d & 1) ? cosf(ang) : sinf(ang);
            const size_t idx = (size_t)row * DMODEL + d;
            g_tgt[idx] = acc;
            __nv_bfloat16 h, l; split_bf16(acc, h, l);
            g_tgt_h[idx] = h; g_tgt_l[idx] = l;
        }
    } else {
        const int j = s - LX;
        if (tid < 6) {
            float v = w[(size_t)b * 2304 + (size_t)j * 6 + tid];
            if (v != v) v = 0.0f;
            float u = v * rinv;
            feat[tid] = fminf(fmaxf(u, -5.0f), 5.0f);
        }
        __syncthreads();
        const float pos = (float)s;
        for (int d = tid; d < DMODEL; d += 256) {
            const float* wr = Wc + (size_t)d * 6;
            float acc = bc[d];
#pragma unroll
            for (int jj = 0; jj < 6; jj++) acc = fmaf(feat[jj], wr[jj], acc);
            float divf = expf((float)(d >> 1) * pefac);
            float ang = pos * divf;
            acc += (d & 1) ? cosf(ang) : sinf(ang);
            const size_t idx = (size_t)row * DMODEL + d;
            g_tgt[idx] = acc;
            __nv_bfloat16 h, l; split_bf16(acc, h, l);
            g_tgt_h[idx] = h; g_tgt_l[idx] = l;
        }
    }
}

// ---------------- residual add + LayerNorm (fp32 + bf16 hi/lo outputs) ----------------
__global__ void add_ln_kernel(const float* __restrict__ gg, const float* __restrict__ bb)
{
    const size_t row = blockIdx.x;
    float* px = g_tgt + row * DMODEL;
    const float* pa = g_tmp + row * DMODEL;
    const int tid = threadIdx.x;
    __shared__ float sred[8];
    float v[4];
    float s = 0.0f;
#pragma unroll
    for (int i = 0; i < 4; i++) {
        int c = tid + i * 256;
        v[i] = px[c] + pa[c];
        s += v[i];
    }
    const float mean = block_sum256(s, sred) * (1.0f / 1024.0f);
    float q = 0.0f;
#pragma unroll
    for (int i = 0; i < 4; i++) { float d = v[i] - mean; q += d * d; }
    const float var = block_sum256(q, sred) * (1.0f / 1024.0f);
    const float inv = rsqrtf(var + 1e-5f);
#pragma unroll
    for (int i = 0; i < 4; i++) {
        int c = tid + i * 256;
        float o = (v[i] - mean) * inv * gg[c] + bb[c];
        px[c] = o;
        __nv_bfloat16 h, l; split_bf16(o, h, l);
        g_tgt_h[row * DMODEL + c] = h;
        g_tgt_l[row * DMODEL + c] = l;
    }
}

// ---------------- final head + MSE loss (single block) ----------------
__global__ void loss_kernel(const float* __restrict__ Wh, const float* __restrict__ bh,
                            const float* __restrict__ y, const float* __restrict__ w,
                            float* __restrict__ out)
{
    const int tid = threadIdx.x;
    __shared__ float sred[8];
    float lsum = 0.0f;
    for (int jz = tid; jz < BATCH * HAM; jz += 256) {
        const int b = jz / HAM, jj = jz % HAM;
        const float* t = g_tgt + ((size_t)b * SEQ + (SEQ - 1)) * DMODEL;
        const float* wr = Wh + (size_t)jj * DMODEL;
        float a0 = 0.f, a1 = 0.f, a2 = 0.f, a3 = 0.f;
        for (int k = 0; k < DMODEL; k += 4) {
            a0 = fmaf(t[k + 0], wr[k + 0], a0);
            a1 = fmaf(t[k + 1], wr[k + 1], a1);
            a2 = fmaf(t[k + 2], wr[k + 2], a2);
            a3 = fmaf(t[k + 3], wr[k + 3], a3);
        }
        const float hat = ((a0 + a1) + (a2 + a3)) + bh[jj];
        const float resid = y[b * HAM + jj] - w[(size_t)b * 2304 + 2160 + jj];
        const float d = hat - resid;
        lsum += d * d;
    }
    const float tot = block_sum256(lsum, sred);
    if (tid == 0) out[0] = tot * (1.0f / (float)(BATCH * HAM));
}

// ---------------- host orchestration ----------------
extern "C" void kernel_launch(void* const* d_in, const int* in_sizes, int n_in,
                              void* d_out, int out_size)
{
    (void)in_sizes; (void)n_in; (void)out_size;
    const float* x      = (const float*)d_in[0];
    const float* w      = (const float*)d_in[1];
    const float* y      = (const float*)d_in[2];
    const float* W_nail = (const float*)d_in[3];
    const float* b_nail = (const float*)d_in[4];
    const float* W_cond = (const float*)d_in[5];
    const float* b_cond = (const float*)d_in[6];
    const float* Wqkv   = (const float*)d_in[7];
    const float* bqkv   = (const float*)d_in[8];
    const float* Wo     = (const float*)d_in[9];
    const float* bo     = (const float*)d_in[10];
    const float* ln1_g  = (const float*)d_in[11];
    const float* ln1_b  = (const float*)d_in[12];
    const float* ln2_g  = (const float*)d_in[13];
    const float* ln2_b  = (const float*)d_in[14];
    const float* W1     = (const float*)d_in[15];
    const float* b1     = (const float*)d_in[16];
    const float* W2     = (const float*)d_in[17];
    const float* b2     = (const float*)d_in[18];
    const float* W_ham  = (const float*)d_in[19];
    const float* b_ham  = (const float*)d_in[20];

    cudaFuncSetAttribute(mma_gemm_kernel, cudaFuncAttributeMaxDynamicSharedMemorySize, GSMEM_BYTES);
    cudaFuncSetAttribute(flash_kernel, cudaFuncAttributeMaxDynamicSharedMemorySize, FA_SMEM);

    float* tmp_p;
    __nv_bfloat16 *tgth_p, *tgtl_p, *qkvh_p, *qkvl_p, *ctxh_p, *ctxl_p, *ffh_p, *ffl_p;
    __nv_bfloat16 *wqkvh_p, *wqkvl_p, *woh_p, *wol_p, *w1h_p, *w1l_p, *w2h_p, *w2l_p;
    cudaGetSymbolAddress((void**)&tmp_p, g_tmp);
    cudaGetSymbolAddress((void**)&tgth_p, g_tgt_h);
    cudaGetSymbolAddress((void**)&tgtl_p, g_tgt_l);
    cudaGetSymbolAddress((void**)&qkvh_p, g_qkv_h);
    cudaGetSymbolAddress((void**)&qkvl_p, g_qkv_l);
    cudaGetSymbolAddress((void**)&ctxh_p, g_ctx_h);
    cudaGetSymbolAddress((void**)&ctxl_p, g_ctx_l);
    cudaGetSymbolAddress((void**)&ffh_p, g_ff_h);
    cudaGetSymbolAddress((void**)&ffl_p, g_ff_l);
    cudaGetSymbolAddress((void**)&wqkvh_p, g_wqkv_h);
    cudaGetSymbolAddress((void**)&wqkvl_p, g_wqkv_l);
    cudaGetSymbolAddress((void**)&woh_p, g_wo_h);
    cudaGetSymbolAddress((void**)&wol_p, g_wo_l);
    cudaGetSymbolAddress((void**)&w1h_p, g_w1_h);
    cudaGetSymbolAddress((void**)&w1l_p, g_w1_l);
    cudaGetSymbolAddress((void**)&w2h_p, g_w2_h);
    cudaGetSymbolAddress((void**)&w2l_p, g_w2_l);

    // weight splits
    {
        int n4;
        n4 = NLAY * 3 * DMODEL * DMODEL / 4;
        split_kernel<<<(n4 + 255) / 256, 256>>>(Wqkv, wqkvh_p, wqkvl_p, n4);
        n4 = NLAY * DMODEL * DMODEL / 4;
        split_kernel<<<(n4 + 255) / 256, 256>>>(Wo, woh_p, wol_p, n4);
        n4 = NLAY * FFDIM * DMODEL / 4;
        split_kernel<<<(n4 + 255) / 256, 256>>>(W1, w1h_p, w1l_p, n4);
        n4 = NLAY * DMODEL * FFDIM / 4;
        split_kernel<<<(n4 + 255) / 256, 256>>>(W2, w2h_p, w2l_p, n4);
    }

    embed_kernel<<<MTOT, 256>>>(x, w, W_nail, b_nail, W_cond, b_cond);

    for (int i = 0; i < NLAY; i++) {
        __nv_bfloat16* Wqkv_h = wqkvh_p + (size_t)i * 3 * DMODEL * DMODEL;
        __nv_bfloat16* Wqkv_l = wqkvl_p + (size_t)i * 3 * DMODEL * DMODEL;
        __nv_bfloat16* Wo_h   = woh_p + (size_t)i * DMODEL * DMODEL;
        __nv_bfloat16* Wo_l   = wol_p + (size_t)i * DMODEL * DMODEL;
        __nv_bfloat16* W1_h   = w1h_p + (size_t)i * FFDIM * DMODEL;
        __nv_bfloat16* W1_l   = w1l_p + (size_t)i * FFDIM * DMODEL;
        __nv_bfloat16* W2_h   = w2h_p + (size_t)i * DMODEL * FFDIM;
        __nv_bfloat16* W2_l   = w2l_p + (size_t)i * DMODEL * FFDIM;

        // QKV: (7168,1024)@(3072,1024)^T -> bf16 hi/lo qkv
        mma_gemm_kernel<<<dim3(12, 56), 256, GSMEM_BYTES>>>(
            tgth_p, tgtl_p, DMODEL, Wqkv_h, Wqkv_l, DMODEL,
            (float*)0, qkvh_p, qkvl_p, 3 * DMODEL, DMODEL,
            bqkv + (size_t)i * 3 * DMODEL, 0, 1);
        // fused attention -> ctx bf16 hi/lo
        flash_kernel<<<dim3(7, BATCH * NHEAD), 256, FA_SMEM>>>(x);
        // O projection -> g_tmp fp32
        mma_gemm_kernel<<<dim3(4, 56), 256, GSMEM_BYTES>>>(
            ctxh_p, ctxl_p, DMODEL, Wo_h, Wo_l, DMODEL,
            tmp_p, (__nv_bfloat16*)0, (__nv_bfloat16*)0, DMODEL, DMODEL,
            bo + (size_t)i * DMODEL, 0, 0);
        add_ln_kernel<<<MTOT, 256>>>(ln1_g + (size_t)i * DMODEL, ln1_b + (size_t)i * DMODEL);
        // FF1 + GELU -> bf16 hi/lo ff
        mma_gemm_kernel<<<dim3(16, 56), 256, GSMEM_BYTES>>>(
            tgth_p, tgtl_p, DMODEL, W1_h, W1_l, DMODEL,
            (float*)0, ffh_p, ffl_p, FFDIM, DMODEL,
            b1 + (size_t)i * FFDIM, 1, 1);
        // FF2 -> g_tmp fp32
        mma_gemm_kernel<<<dim3(4, 56), 256, GSMEM_BYTES>>>(
            ffh_p, ffl_p, FFDIM, W2_h, W2_l, FFDIM,
            tmp_p, (__nv_bfloat16*)0, (__nv_bfloat16*)0, DMODEL, FFDIM,
            b2 + (size_t)i * DMODEL, 0, 0);
        add_ln_kernel<<<MTOT, 256>>>(ln2_g + (size_t)i * DMODEL, ln2_b + (size_t)i * DMODEL);
    }

    loss_kernel<<<1, 256>>>(W_ham, b_ham, y, w, (float*)d_out);
}